// round 11
// baseline (speedup 1.0000x reference)
#include <cuda_runtime.h>
#include <cuda_bf16.h>
#include <cstdint>

// VectorQuantizer: z (8,128,4096) f32, codebook (1024,128) f32.
// Output layout (confirmed): concatenated f32
//   [0)        z_q_out (B,D,T)   4,194,304
//   [4194304)  codes   (B,T)        32,768
//   [4227072)  loss                      1
//   [4227073)  dist    (B,T,1024) 33,554,432  (odd float offset: NOT 16B aligned)

#define DD      128
#define NCODES  1024
#define TT      4096
#define BB      8
#define BT      (BB*TT)          // 32768
#define ZQ_ELEMS (BB*DD*TT)
#define OUT_FULL (ZQ_ELEMS + BT + 1 + (long long)BT*NCODES)
#define PREPZ_SMEM (DD * 130 * 4)    // 66560 bytes (dynamic)
// GEMM smem: Ah 32K | Al 32K | Bh 16K | Bl 16K = 96KB dynamic
#define GEMM_SMEM  98304

// bf16 fragment-major prepack (mma.m16n8k16 row.col):
// A tile (128 rows): [mt(8)][ks(8)][lane(32)] x uint4
//   g = mt*16 + lane>>2, k0 = ks*16 + (lane&3)*2
//   a0={A[g][k0],A[g][k0+1]} a1={A[g+8][k0],..} a2={A[g][k0+8],..} a3={A[g+8][k0+8],..}
// B tile (64 codes): [nt(8)][ks(8)][lane(32)] x uint2
//   n = nt*8 + lane>>2; b0={C[n][k0],C[n][k0+1]} b1={C[n][k0+8],C[n][k0+9]}
__device__ __align__(16) uint4 g_ah[(size_t)256 * 2048];   // 8 MB (z hi)
__device__ __align__(16) uint4 g_al[(size_t)256 * 2048];   // 8 MB (z lo)
__device__ __align__(16) uint2 g_bh[16 * 2048];            // 256 KB (cb hi)
__device__ __align__(16) uint2 g_bl[16 * 2048];            // 256 KB (cb lo)
__device__ float  g_r2[BT];
__device__ float  g_c2[NCODES];
__device__ float  g_minv[BT * 16];
__device__ int    g_mini[BT * 16];
__device__ int    g_codes[BT];
__device__ double g_partial[256];

__device__ __forceinline__ uint32_t smem_u32(const void* p) {
    uint32_t a;
    asm("{ .reg .u64 t; cvta.to.shared.u64 t, %1; cvt.u32.u64 %0, t; }" : "=r"(a) : "l"(p));
    return a;
}
__device__ __forceinline__ uint32_t packbf(float x0, float x1) {   // x0 -> low half
    unsigned short h0 = __bfloat16_as_ushort(__float2bfloat16(x0));
    unsigned short h1 = __bfloat16_as_ushort(__float2bfloat16(x1));
    return ((uint32_t)h1 << 16) | h0;
}
__device__ __forceinline__ float bfres(float x) {                   // residual after bf16 hi
    return x - __bfloat162float(__float2bfloat16(x));
}

// --------------------------------------------------- prep z: transpose + split frags + r2
__global__ __launch_bounds__(128)
void prep_z(const float* __restrict__ z) {
    extern __shared__ float stg[];          // [DD][130]
    const int tid = threadIdx.x, bx = blockIdx.x;
    const int b = bx >> 5, t0 = (bx & 31) * 128;
    const float* zb = z + (size_t)b * DD * TT + t0;
    for (int idx = tid; idx < DD * 128; idx += 128) {
        int d = idx >> 7, tl = idx & 127;
        stg[d * 130 + tl] = zb[(size_t)d * TT + tl];
    }
    __syncthreads();
    {
        double r2 = 0.0;
        #pragma unroll 8
        for (int d = 0; d < DD; ++d) { float v = stg[d * 130 + tid]; r2 += (double)v * v; }
        g_r2[bx * 128 + tid] = (float)r2;
    }
    uint4* dh = g_ah + (size_t)bx * 2048;
    uint4* dl = g_al + (size_t)bx * 2048;
    #pragma unroll 4
    for (int i = 0; i < 16; ++i) {
        int fi = tid + i * 128;                       // 0..2047
        int lane = fi & 31, ks = (fi >> 5) & 7, mt = fi >> 8;
        int g = mt * 16 + (lane >> 2);
        int k0 = ks * 16 + (lane & 3) * 2;
        float x00 = stg[k0 * 130 + g],        x01 = stg[(k0 + 1) * 130 + g];
        float x10 = stg[k0 * 130 + g + 8],    x11 = stg[(k0 + 1) * 130 + g + 8];
        float x20 = stg[(k0 + 8) * 130 + g],  x21 = stg[(k0 + 9) * 130 + g];
        float x30 = stg[(k0 + 8) * 130 + g + 8], x31 = stg[(k0 + 9) * 130 + g + 8];
        dh[fi] = make_uint4(packbf(x00, x01), packbf(x10, x11), packbf(x20, x21), packbf(x30, x31));
        dl[fi] = make_uint4(packbf(bfres(x00), bfres(x01)), packbf(bfres(x10), bfres(x11)),
                            packbf(bfres(x20), bfres(x21)), packbf(bfres(x30), bfres(x31)));
    }
}

// --------------------------------------------------- prep codebook frags (hi + lo)
__global__ __launch_bounds__(256)
void prep_c(const float* __restrict__ cb) {
    const int idx = blockIdx.x * 256 + threadIdx.x;   // < 32768
    const int r = idx & 2047, nb = idx >> 11;
    const int lane = r & 31, ks = (r >> 5) & 7, nt = r >> 8;
    const int n = nb * 64 + nt * 8 + (lane >> 2);
    const int k0 = ks * 16 + (lane & 3) * 2;
    const float* row = cb + (size_t)n * DD;
    float x00 = row[k0],     x01 = row[k0 + 1];
    float x10 = row[k0 + 8], x11 = row[k0 + 9];
    g_bh[idx] = make_uint2(packbf(x00, x01), packbf(x10, x11));
    g_bl[idx] = make_uint2(packbf(bfres(x00), bfres(x01)), packbf(bfres(x10), bfres(x11)));
}

__global__ void c2_kernel(const float* __restrict__ cb) {
    int i = blockIdx.x * blockDim.x + threadIdx.x;
    if (i < NCODES) {
        const float* r = cb + (size_t)i * DD;
        double s = 0.0;
        #pragma unroll 8
        for (int d = 0; d < DD; ++d) { float v = r[d]; s += (double)v * (double)v; }
        g_c2[i] = (float)s;
    }
}

// --------------------------------------------------- bf16-split dist GEMM + partial argmin
// grid (256, 16): bx = 128-row tile, by = 64-code tile. 256 thr = 8 warps (2 x 4).
// warp tile 64x16. dot = zh*ch + zl*ch + zh*cl.
__global__ __launch_bounds__(256, 2)
void vq_gemm(float* __restrict__ dist) {
    extern __shared__ __align__(16) unsigned char dsm[];
    __shared__ float r2s[128], c2s[64];
    __shared__ float redV[512];
    __shared__ int   redI[512];

    const int tid = threadIdx.x, lane = tid & 31, wid = tid >> 5;
    const int wm = wid & 1, wn = wid >> 1;          // rows wm*64, cols wn*16
    const int bx = blockIdx.x, by = blockIdx.y;
    const int rowbase = bx * 128, colbase = by * 64;

    const uint32_t sB = smem_u32(dsm);
    const char* gAh = (const char*)(g_ah + (size_t)bx * 2048);
    const char* gAl = (const char*)(g_al + (size_t)bx * 2048);
    const char* gBh = (const char*)(g_bh + (size_t)by * 2048);
    const char* gBl = (const char*)(g_bl + (size_t)by * 2048);
    #pragma unroll
    for (int i = 0; i < 8; ++i) {
        uint32_t o = (tid + i * 256) * 16;
        asm volatile("cp.async.cg.shared.global [%0], [%1], 16;" :: "r"(sB + o), "l"(gAh + o));
        asm volatile("cp.async.cg.shared.global [%0], [%1], 16;" :: "r"(sB + 32768 + o), "l"(gAl + o));
    }
    #pragma unroll
    for (int i = 0; i < 4; ++i) {
        uint32_t o = (tid + i * 256) * 16;
        asm volatile("cp.async.cg.shared.global [%0], [%1], 16;" :: "r"(sB + 65536 + o), "l"(gBh + o));
        asm volatile("cp.async.cg.shared.global [%0], [%1], 16;" :: "r"(sB + 81920 + o), "l"(gBl + o));
    }
    asm volatile("cp.async.commit_group;" ::: "memory");

    if (tid < 128) r2s[tid] = g_r2[rowbase + tid];
    if (tid < 64)  c2s[tid] = g_c2[colbase + tid];

    asm volatile("cp.async.wait_group 0;" ::: "memory");
    __syncthreads();

    float acc[4][2][4];
    #pragma unroll
    for (int i = 0; i < 4; ++i)
        #pragma unroll
        for (int j = 0; j < 2; ++j)
            #pragma unroll
            for (int k = 0; k < 4; ++k) acc[i][j][k] = 0.0f;

    #pragma unroll
    for (int seg = 0; seg < 3; ++seg) {
        const unsigned char* aB = dsm + ((seg == 1) ? 32768 : 0);        // Ah, Al, Ah
        const unsigned char* bB = dsm + ((seg == 2) ? 81920 : 65536);    // Bh, Bh, Bl
        #pragma unroll
        for (int ks = 0; ks < 8; ++ks) {
            uint4 af[4]; uint2 bf[2];
            #pragma unroll
            for (int mt = 0; mt < 4; ++mt)
                af[mt] = *(const uint4*)(aB + (size_t)(((wm * 4 + mt) * 8 + ks) * 32 + lane) * 16);
            #pragma unroll
            for (int nt = 0; nt < 2; ++nt)
                bf[nt] = *(const uint2*)(bB + (size_t)(((wn * 2 + nt) * 8 + ks) * 32 + lane) * 8);
            #pragma unroll
            for (int mt = 0; mt < 4; ++mt)
                #pragma unroll
                for (int nt = 0; nt < 2; ++nt)
                    asm volatile(
                        "mma.sync.aligned.m16n8k16.row.col.f32.bf16.bf16.f32 "
                        "{%0,%1,%2,%3}, {%4,%5,%6,%7}, {%8,%9}, {%0,%1,%2,%3};"
                        : "+f"(acc[mt][nt][0]), "+f"(acc[mt][nt][1]),
                          "+f"(acc[mt][nt][2]), "+f"(acc[mt][nt][3])
                        : "r"(af[mt].x), "r"(af[mt].y), "r"(af[mt].z), "r"(af[mt].w),
                          "r"(bf[nt].x), "r"(bf[nt].y));
        }
    }

    // epilogue: dist = (r2 - 2*dot) + c2, stores + per-row argmin
    #pragma unroll
    for (int mt = 0; mt < 4; ++mt) {
        const int r0 = wm * 64 + mt * 16 + (lane >> 2);
        const int r1 = r0 + 8;
        const float r2a = r2s[r0], r2b = r2s[r1];
        float v0 = 3.4e38f, v1 = 3.4e38f; int i0 = 0, i1 = 0;
        float* dp0 = dist ? dist + (size_t)(rowbase + r0) * NCODES + colbase : nullptr;
        float* dp1 = dist ? dist + (size_t)(rowbase + r1) * NCODES + colbase : nullptr;
        #pragma unroll
        for (int nt = 0; nt < 2; ++nt) {
            const int cl0 = wn * 16 + nt * 8 + (lane & 3) * 2;   // local col 0..63
            const float c20 = c2s[cl0], c21 = c2s[cl0 + 1];
            float d00 = __fadd_rn(__fsub_rn(r2a, __fmul_rn(2.0f, acc[mt][nt][0])), c20);
            float d01 = __fadd_rn(__fsub_rn(r2a, __fmul_rn(2.0f, acc[mt][nt][1])), c21);
            float d10 = __fadd_rn(__fsub_rn(r2b, __fmul_rn(2.0f, acc[mt][nt][2])), c20);
            float d11 = __fadd_rn(__fsub_rn(r2b, __fmul_rn(2.0f, acc[mt][nt][3])), c21);
            if (dp0) { __stcs(dp0 + cl0, d00); __stcs(dp0 + cl0 + 1, d01);
                       __stcs(dp1 + cl0, d10); __stcs(dp1 + cl0 + 1, d11); }
            if (d00 < v0) { v0 = d00; i0 = cl0; }
            if (d01 < v0) { v0 = d01; i0 = cl0 + 1; }
            if (d10 < v1) { v1 = d10; i1 = cl0; }
            if (d11 < v1) { v1 = d11; i1 = cl0 + 1; }
        }
        #pragma unroll
        for (int off = 1; off <= 2; off <<= 1) {
            float ov = __shfl_xor_sync(0xffffffff, v0, off);
            int   oi = __shfl_xor_sync(0xffffffff, i0, off);
            if (ov < v0 || (ov == v0 && oi < i0)) { v0 = ov; i0 = oi; }
            ov = __shfl_xor_sync(0xffffffff, v1, off);
            oi = __shfl_xor_sync(0xffffffff, i1, off);
            if (ov < v1 || (ov == v1 && oi < i1)) { v1 = ov; i1 = oi; }
        }
        if ((lane & 3) == 0) {
            redV[r0 * 4 + wn] = v0; redI[r0 * 4 + wn] = i0;
            redV[r1 * 4 + wn] = v1; redI[r1 * 4 + wn] = i1;
        }
    }
    __syncthreads();
    if (tid < 128) {
        float bv = redV[tid * 4]; int bi = redI[tid * 4];
        #pragma unroll
        for (int w = 1; w < 4; ++w) {
            float v = redV[tid * 4 + w]; int ii = redI[tid * 4 + w];
            if (v < bv || (v == bv && ii < bi)) { bv = v; bi = ii; }
        }
        g_minv[(size_t)(rowbase + tid) * 16 + by] = bv;
        g_mini[(size_t)(rowbase + tid) * 16 + by] = colbase + bi;
    }
}

// --------------------------------------------------- cross-chunk argmin + loss partials
__global__ __launch_bounds__(128)
void combine(float* __restrict__ codesF) {
    __shared__ double s[128];
    const int tid = threadIdx.x;
    const int row = blockIdx.x * 128 + tid;
    float bv = g_minv[(size_t)row * 16]; int bi = g_mini[(size_t)row * 16];
    #pragma unroll
    for (int c = 1; c < 16; ++c) {
        float v = g_minv[(size_t)row * 16 + c]; int ii = g_mini[(size_t)row * 16 + c];
        if (v < bv || (v == bv && ii < bi)) { bv = v; bi = ii; }
    }
    g_codes[row] = bi;
    if (codesF) codesF[row] = (float)bi;
    s[tid] = (double)bv;
    __syncthreads();
    for (int o = 64; o; o >>= 1) {
        if (tid < o) s[tid] += s[tid + o];
        __syncthreads();
    }
    if (tid == 0) g_partial[blockIdx.x] = s[0];
}

// --------------------------------------------------- z_q gather (B,D,T)
__global__ void zq_kernel(const float* __restrict__ cb, float* __restrict__ zq) {
    int idx = blockIdx.x * blockDim.x + threadIdx.x;
    int t = idx & (TT - 1);
    int d = (idx >> 12) & (DD - 1);
    int b = idx >> 19;
    int code = g_codes[(b << 12) + t];
    zq[idx] = __ldg(&cb[(size_t)code * DD + d]);
}

// --------------------------------------------------- loss finalize
__global__ void fin_kernel(float* __restrict__ loss) {
    __shared__ double s[256];
    s[threadIdx.x] = g_partial[threadIdx.x];
    __syncthreads();
    for (int o = 128; o; o >>= 1) {
        if (threadIdx.x < o) s[threadIdx.x] += s[threadIdx.x + o];
        __syncthreads();
    }
    if (threadIdx.x == 0) *loss = (float)(1.25 * s[0] / (double)ZQ_ELEMS);
}

// --------------------------------------------------- launcher
extern "C" void kernel_launch(void* const* d_in, const int* in_sizes, int n_in,
                              void* d_out, int out_size) {
    const float* z  = (const float*)d_in[0];
    const float* cb = (const float*)d_in[1];
    float* out = (float*)d_out;

    float* zq     = out;
    float* codesF = nullptr;
    float* lossF  = nullptr;
    float* dist   = nullptr;
    if ((long long)out_size >= OUT_FULL) {
        codesF = out + ZQ_ELEMS;
        lossF  = codesF + BT;
        dist   = lossF + 1;
    }

    cudaFuncSetAttribute(prep_z, cudaFuncAttributeMaxDynamicSharedMemorySize, PREPZ_SMEM);
    cudaFuncSetAttribute(vq_gemm, cudaFuncAttributeMaxDynamicSharedMemorySize, GEMM_SMEM);

    prep_z<<<256, 128, PREPZ_SMEM>>>(z);
    prep_c<<<128, 256>>>(cb);
    c2_kernel<<<(NCODES + 255) / 256, 256>>>(cb);
    vq_gemm<<<dim3(256, 16), 256, GEMM_SMEM>>>(dist);
    combine<<<256, 128>>>(codesF);
    zq_kernel<<<ZQ_ELEMS / 256, 256>>>(cb, zq);
    if (lossF) fin_kernel<<<1, 256>>>(lossF);
}

// round 13
// speedup vs baseline: 1.3628x; 1.3628x over previous
#include <cuda_runtime.h>
#include <cuda_bf16.h>
#include <cstdint>

// VectorQuantizer: z (8,128,4096) f32, codebook (1024,128) f32.
// Output layout (confirmed): concatenated f32
//   [0)        z_q_out (B,D,T)   4,194,304
//   [4194304)  codes   (B,T)        32,768
//   [4227072)  loss                      1
//   [4227073)  dist    (B,T,1024) 33,554,432  (odd float offset: NOT 16B aligned)

#define DD      128
#define NCODES  1024
#define TT      4096
#define BB      8
#define BT      (BB*TT)          // 32768
#define ZQ_ELEMS (BB*DD*TT)
#define OUT_FULL (ZQ_ELEMS + BT + 1 + (long long)BT*NCODES)
#define PREPZ_SMEM (DD * 130 * 4)    // 66560 bytes (dynamic)
// GEMM smem: Ah 32K | Al 32K | Bh 16K | Bl 16K = 96KB dynamic (A region reused as dist stage)
#define GEMM_SMEM  98304

// bf16 fragment-major prepack (mma.m16n8k16 row.col):
// A tile (128 rows): [mt(8)][ks(8)][lane(32)] x uint4
//   g = mt*16 + lane>>2, k0 = ks*16 + (lane&3)*2
//   a0={A[g][k0],A[g][k0+1]} a1={A[g+8][k0],..} a2={A[g][k0+8],..} a3={A[g+8][k0+8],..}
// B tile (64 codes): [nt(8)][ks(8)][lane(32)] x uint2
//   n = nt*8 + lane>>2; b0={C[n][k0],C[n][k0+1]} b1={C[n][k0+8],C[n][k0+9]}
__device__ __align__(16) uint4 g_ah[(size_t)256 * 2048];   // 8 MB (z hi)
__device__ __align__(16) uint4 g_al[(size_t)256 * 2048];   // 8 MB (z lo)
__device__ __align__(16) uint2 g_bh[16 * 2048];            // 256 KB (cb hi)
__device__ __align__(16) uint2 g_bl[16 * 2048];            // 256 KB (cb lo)
__device__ float  g_r2[BT];
__device__ float  g_c2[NCODES];
__device__ float  g_minv[BT * 16];
__device__ int    g_mini[BT * 16];
__device__ int    g_codes[BT];
__device__ double g_partial[256];

__device__ __forceinline__ uint32_t smem_u32(const void* p) {
    uint32_t a;
    asm("{ .reg .u64 t; cvta.to.shared.u64 t, %1; cvt.u32.u64 %0, t; }" : "=r"(a) : "l"(p));
    return a;
}
__device__ __forceinline__ uint32_t packbf(float x0, float x1) {   // x0 -> low half
    unsigned short h0 = __bfloat16_as_ushort(__float2bfloat16(x0));
    unsigned short h1 = __bfloat16_as_ushort(__float2bfloat16(x1));
    return ((uint32_t)h1 << 16) | h0;
}
__device__ __forceinline__ float bfres(float x) {                   // residual after bf16 hi
    return x - __bfloat162float(__float2bfloat16(x));
}

// --------------------------------------------------- prep z: transpose + split frags + r2
__global__ __launch_bounds__(128)
void prep_z(const float* __restrict__ z) {
    extern __shared__ float stg[];          // [DD][130]
    const int tid = threadIdx.x, bx = blockIdx.x;
    const int b = bx >> 5, t0 = (bx & 31) * 128;
    const float* zb = z + (size_t)b * DD * TT + t0;
    for (int idx = tid; idx < DD * 128; idx += 128) {
        int d = idx >> 7, tl = idx & 127;
        stg[d * 130 + tl] = zb[(size_t)d * TT + tl];
    }
    __syncthreads();
    {
        double r2 = 0.0;
        #pragma unroll 8
        for (int d = 0; d < DD; ++d) { float v = stg[d * 130 + tid]; r2 += (double)v * v; }
        g_r2[bx * 128 + tid] = (float)r2;
    }
    uint4* dh = g_ah + (size_t)bx * 2048;
    uint4* dl = g_al + (size_t)bx * 2048;
    #pragma unroll 4
    for (int i = 0; i < 16; ++i) {
        int fi = tid + i * 128;                       // 0..2047
        int lane = fi & 31, ks = (fi >> 5) & 7, mt = fi >> 8;
        int g = mt * 16 + (lane >> 2);
        int k0 = ks * 16 + (lane & 3) * 2;
        float x00 = stg[k0 * 130 + g],        x01 = stg[(k0 + 1) * 130 + g];
        float x10 = stg[k0 * 130 + g + 8],    x11 = stg[(k0 + 1) * 130 + g + 8];
        float x20 = stg[(k0 + 8) * 130 + g],  x21 = stg[(k0 + 9) * 130 + g];
        float x30 = stg[(k0 + 8) * 130 + g + 8], x31 = stg[(k0 + 9) * 130 + g + 8];
        dh[fi] = make_uint4(packbf(x00, x01), packbf(x10, x11), packbf(x20, x21), packbf(x30, x31));
        dl[fi] = make_uint4(packbf(bfres(x00), bfres(x01)), packbf(bfres(x10), bfres(x11)),
                            packbf(bfres(x20), bfres(x21)), packbf(bfres(x30), bfres(x31)));
    }
}

// --------------------------------------------------- prep codebook frags (hi + lo) + c2
__global__ __launch_bounds__(256)
void prep_c(const float* __restrict__ cb) {
    const int idx = blockIdx.x * 256 + threadIdx.x;   // < 32768
    const int r = idx & 2047, nb = idx >> 11;
    const int lane = r & 31, ks = (r >> 5) & 7, nt = r >> 8;
    const int n = nb * 64 + nt * 8 + (lane >> 2);
    const int k0 = ks * 16 + (lane & 3) * 2;
    const float* row = cb + (size_t)n * DD;
    float x00 = row[k0],     x01 = row[k0 + 1];
    float x10 = row[k0 + 8], x11 = row[k0 + 9];
    g_bh[idx] = make_uint2(packbf(x00, x01), packbf(x10, x11));
    g_bl[idx] = make_uint2(packbf(bfres(x00), bfres(x01)), packbf(bfres(x10), bfres(x11)));
    if (idx < NCODES) {
        const float* rr = cb + (size_t)idx * DD;
        double s = 0.0;
        #pragma unroll 8
        for (int d = 0; d < DD; ++d) { float v = rr[d]; s += (double)v * (double)v; }
        g_c2[idx] = (float)s;
    }
}

// --------------------------------------------------- bf16-split dist GEMM + partial argmin
// grid (256, 16): bx = 128-row tile, by = 64-code tile. 256 thr = 8 warps (2 x 4).
// warp tile 64x16. dot = zh*ch + zl*ch + zh*cl.  Merged segs + A double-buffer.
__global__ __launch_bounds__(256, 2)
void vq_gemm(float* __restrict__ dist) {
    extern __shared__ __align__(16) unsigned char dsm[];
    __shared__ float r2s[128], c2s[64];
    __shared__ float redV[512];
    __shared__ int   redI[512];

    const int tid = threadIdx.x, lane = tid & 31, wid = tid >> 5;
    const int wm = wid & 1, wn = wid >> 1;          // rows wm*64, cols wn*16
    const int bx = blockIdx.x, by = blockIdx.y;
    const int rowbase = bx * 128, colbase = by * 64;

    const uint32_t sB = smem_u32(dsm);
    const char* gAh = (const char*)(g_ah + (size_t)bx * 2048);
    const char* gAl = (const char*)(g_al + (size_t)bx * 2048);
    const char* gBh = (const char*)(g_bh + (size_t)by * 2048);
    const char* gBl = (const char*)(g_bl + (size_t)by * 2048);
    #pragma unroll
    for (int i = 0; i < 8; ++i) {
        uint32_t o = (tid + i * 256) * 16;
        asm volatile("cp.async.cg.shared.global [%0], [%1], 16;" :: "r"(sB + o), "l"(gAh + o));
        asm volatile("cp.async.cg.shared.global [%0], [%1], 16;" :: "r"(sB + 32768 + o), "l"(gAl + o));
    }
    #pragma unroll
    for (int i = 0; i < 4; ++i) {
        uint32_t o = (tid + i * 256) * 16;
        asm volatile("cp.async.cg.shared.global [%0], [%1], 16;" :: "r"(sB + 65536 + o), "l"(gBh + o));
        asm volatile("cp.async.cg.shared.global [%0], [%1], 16;" :: "r"(sB + 81920 + o), "l"(gBl + o));
    }
    asm volatile("cp.async.commit_group;" ::: "memory");

    if (tid < 128) r2s[tid] = g_r2[rowbase + tid];
    if (tid < 64)  c2s[tid] = g_c2[colbase + tid];

    asm volatile("cp.async.wait_group 0;" ::: "memory");
    __syncthreads();

    float acc[4][2][4];
    #pragma unroll
    for (int i = 0; i < 4; ++i)
        #pragma unroll
        for (int j = 0; j < 2; ++j)
            #pragma unroll
            for (int k = 0; k < 4; ++k) acc[i][j][k] = 0.0f;

    // frag smem index helpers
    #define A_OFF(mt, kk) ((size_t)((((wm) * 4 + (mt)) * 8 + (kk)) * 32 + lane) * 16)
    #define B_OFF(nt, kk) ((size_t)((((wn) * 2 + (nt)) * 8 + (kk)) * 32 + lane) * 8)

    uint4 afh[2][4], afl[2][4];
    #pragma unroll
    for (int mt = 0; mt < 4; ++mt) {
        afh[0][mt] = *(const uint4*)(dsm + A_OFF(mt, 0));
        afl[0][mt] = *(const uint4*)(dsm + 32768 + A_OFF(mt, 0));
    }

    #pragma unroll
    for (int ks = 0; ks < 8; ++ks) {
        const int cur = ks & 1, nxt = cur ^ 1;
        uint2 bfh[2], bfl[2];
        #pragma unroll
        for (int nt = 0; nt < 2; ++nt) {
            bfh[nt] = *(const uint2*)(dsm + 65536 + B_OFF(nt, ks));
            bfl[nt] = *(const uint2*)(dsm + 81920 + B_OFF(nt, ks));
        }
        if (ks < 7) {
            #pragma unroll
            for (int mt = 0; mt < 4; ++mt) {
                afh[nxt][mt] = *(const uint4*)(dsm + A_OFF(mt, ks + 1));
                afl[nxt][mt] = *(const uint4*)(dsm + 32768 + A_OFF(mt, ks + 1));
            }
        }
        #pragma unroll
        for (int mt = 0; mt < 4; ++mt)
            #pragma unroll
            for (int nt = 0; nt < 2; ++nt) {
                asm volatile(
                    "mma.sync.aligned.m16n8k16.row.col.f32.bf16.bf16.f32 "
                    "{%0,%1,%2,%3}, {%4,%5,%6,%7}, {%8,%9}, {%0,%1,%2,%3};"
                    : "+f"(acc[mt][nt][0]), "+f"(acc[mt][nt][1]),
                      "+f"(acc[mt][nt][2]), "+f"(acc[mt][nt][3])
                    : "r"(afh[cur][mt].x), "r"(afh[cur][mt].y), "r"(afh[cur][mt].z), "r"(afh[cur][mt].w),
                      "r"(bfh[nt].x), "r"(bfh[nt].y));
                asm volatile(
                    "mma.sync.aligned.m16n8k16.row.col.f32.bf16.bf16.f32 "
                    "{%0,%1,%2,%3}, {%4,%5,%6,%7}, {%8,%9}, {%0,%1,%2,%3};"
                    : "+f"(acc[mt][nt][0]), "+f"(acc[mt][nt][1]),
                      "+f"(acc[mt][nt][2]), "+f"(acc[mt][nt][3])
                    : "r"(afl[cur][mt].x), "r"(afl[cur][mt].y), "r"(afl[cur][mt].z), "r"(afl[cur][mt].w),
                      "r"(bfh[nt].x), "r"(bfh[nt].y));
                asm volatile(
                    "mma.sync.aligned.m16n8k16.row.col.f32.bf16.bf16.f32 "
                    "{%0,%1,%2,%3}, {%4,%5,%6,%7}, {%8,%9}, {%0,%1,%2,%3};"
                    : "+f"(acc[mt][nt][0]), "+f"(acc[mt][nt][1]),
                      "+f"(acc[mt][nt][2]), "+f"(acc[mt][nt][3])
                    : "r"(afh[cur][mt].x), "r"(afh[cur][mt].y), "r"(afh[cur][mt].z), "r"(afh[cur][mt].w),
                      "r"(bfl[nt].x), "r"(bfl[nt].y));
            }
    }
    #undef A_OFF
    #undef B_OFF

    __syncthreads();   // mainloop frag reads done in ALL warps before A region reuse

    // epilogue: dist = (r2 - 2*dot) + c2; stage into smem (row stride 65) + argmin
    float* stg = (float*)dsm;                 // 128 x 65 f32 = 33.3KB (fits A region + slack)
    #pragma unroll
    for (int mt = 0; mt < 4; ++mt) {
        const int r0 = wm * 64 + mt * 16 + (lane >> 2);
        const int r1 = r0 + 8;
        const float r2a = r2s[r0], r2b = r2s[r1];
        float v0 = 3.4e38f, v1 = 3.4e38f; int i0 = 0, i1 = 0;
        #pragma unroll
        for (int nt = 0; nt < 2; ++nt) {
            const int cl0 = wn * 16 + nt * 8 + (lane & 3) * 2;   // local col 0..63
            const float c20 = c2s[cl0], c21 = c2s[cl0 + 1];
            float d00 = __fadd_rn(__fsub_rn(r2a, __fmul_rn(2.0f, acc[mt][nt][0])), c20);
            float d01 = __fadd_rn(__fsub_rn(r2a, __fmul_rn(2.0f, acc[mt][nt][1])), c21);
            float d10 = __fadd_rn(__fsub_rn(r2b, __fmul_rn(2.0f, acc[mt][nt][2])), c20);
            float d11 = __fadd_rn(__fsub_rn(r2b, __fmul_rn(2.0f, acc[mt][nt][3])), c21);
            stg[r0 * 65 + cl0] = d00; stg[r0 * 65 + cl0 + 1] = d01;
            stg[r1 * 65 + cl0] = d10; stg[r1 * 65 + cl0 + 1] = d11;
            if (d00 < v0) { v0 = d00; i0 = cl0; }
            if (d01 < v0) { v0 = d01; i0 = cl0 + 1; }
            if (d10 < v1) { v1 = d10; i1 = cl0; }
            if (d11 < v1) { v1 = d11; i1 = cl0 + 1; }
        }
        #pragma unroll
        for (int off = 1; off <= 2; off <<= 1) {
            float ov = __shfl_xor_sync(0xffffffff, v0, off);
            int   oi = __shfl_xor_sync(0xffffffff, i0, off);
            if (ov < v0 || (ov == v0 && oi < i0)) { v0 = ov; i0 = oi; }
            ov = __shfl_xor_sync(0xffffffff, v1, off);
            oi = __shfl_xor_sync(0xffffffff, i1, off);
            if (ov < v1 || (ov == v1 && oi < i1)) { v1 = ov; i1 = oi; }
        }
        if ((lane & 3) == 0) {
            redV[r0 * 4 + wn] = v0; redI[r0 * 4 + wn] = i0;
            redV[r1 * 4 + wn] = v1; redI[r1 * 4 + wn] = i1;
        }
    }
    __syncthreads();

    // coalesced dist write-out: warp stores 32 consecutive floats per instr
    if (dist) {
        float* dbase = dist + (size_t)rowbase * NCODES + colbase;
        #pragma unroll
        for (int i = 0; i < 32; ++i) {
            int e = i * 256 + tid;            // 0..8191
            int r = e >> 6, c = e & 63;
            __stcs(dbase + (size_t)r * NCODES + c, stg[r * 65 + c]);
        }
    }

    if (tid < 128) {
        float bv = redV[tid * 4]; int bi = redI[tid * 4];
        #pragma unroll
        for (int w = 1; w < 4; ++w) {
            float v = redV[tid * 4 + w]; int ii = redI[tid * 4 + w];
            if (v < bv || (v == bv && ii < bi)) { bv = v; bi = ii; }
        }
        g_minv[(size_t)(rowbase + tid) * 16 + by] = bv;
        g_mini[(size_t)(rowbase + tid) * 16 + by] = colbase + bi;
    }
}

// --------------------------------------------------- cross-chunk argmin + loss partials
__global__ __launch_bounds__(128)
void combine(float* __restrict__ codesF) {
    __shared__ double s[128];
    const int tid = threadIdx.x;
    const int row = blockIdx.x * 128 + tid;
    float bv = g_minv[(size_t)row * 16]; int bi = g_mini[(size_t)row * 16];
    #pragma unroll
    for (int c = 1; c < 16; ++c) {
        float v = g_minv[(size_t)row * 16 + c]; int ii = g_mini[(size_t)row * 16 + c];
        if (v < bv || (v == bv && ii < bi)) { bv = v; bi = ii; }
    }
    g_codes[row] = bi;
    if (codesF) codesF[row] = (float)bi;
    s[tid] = (double)bv;
    __syncthreads();
    for (int o = 64; o; o >>= 1) {
        if (tid < o) s[tid] += s[tid + o];
        __syncthreads();
    }
    if (tid == 0) g_partial[blockIdx.x] = s[0];
}

// --------------------------------------------------- z_q gather (B,D,T)
__global__ void zq_kernel(const float* __restrict__ cb, float* __restrict__ zq) {
    int idx = blockIdx.x * blockDim.x + threadIdx.x;
    int t = idx & (TT - 1);
    int d = (idx >> 12) & (DD - 1);
    int b = idx >> 19;
    int code = g_codes[(b << 12) + t];
    zq[idx] = __ldg(&cb[(size_t)code * DD + d]);
}

// --------------------------------------------------- loss finalize
__global__ void fin_kernel(float* __restrict__ loss) {
    __shared__ double s[256];
    s[threadIdx.x] = g_partial[threadIdx.x];
    __syncthreads();
    for (int o = 128; o; o >>= 1) {
        if (threadIdx.x < o) s[threadIdx.x] += s[threadIdx.x + o];
        __syncthreads();
    }
    if (threadIdx.x == 0) *loss = (float)(1.25 * s[0] / (double)ZQ_ELEMS);
}

// --------------------------------------------------- launcher
extern "C" void kernel_launch(void* const* d_in, const int* in_sizes, int n_in,
                              void* d_out, int out_size) {
    const float* z  = (const float*)d_in[0];
    const float* cb = (const float*)d_in[1];
    float* out = (float*)d_out;

    float* zq     = out;
    float* codesF = nullptr;
    float* lossF  = nullptr;
    float* dist   = nullptr;
    if ((long long)out_size >= OUT_FULL) {
        codesF = out + ZQ_ELEMS;
        lossF  = codesF + BT;
        dist   = lossF + 1;
    }

    cudaFuncSetAttribute(prep_z, cudaFuncAttributeMaxDynamicSharedMemorySize, PREPZ_SMEM);
    cudaFuncSetAttribute(vq_gemm, cudaFuncAttributeMaxDynamicSharedMemorySize, GEMM_SMEM);

    prep_z<<<256, 128, PREPZ_SMEM>>>(z);
    prep_c<<<128, 256>>>(cb);
    vq_gemm<<<dim3(256, 16), 256, GEMM_SMEM>>>(dist);
    combine<<<256, 128>>>(codesF);
    zq_kernel<<<ZQ_ELEMS / 256, 256>>>(cb, zq);
    if (lossF) fin_kernel<<<1, 256>>>(lossF);
}

// round 15
// speedup vs baseline: 1.3630x; 1.0002x over previous
#include <cuda_runtime.h>
#include <cuda_bf16.h>
#include <cstdint>

// VectorQuantizer: z (8,128,4096) f32, codebook (1024,128) f32.
// Output layout (confirmed): concatenated f32
//   [0)        z_q_out (B,D,T)   4,194,304
//   [4194304)  codes   (B,T)        32,768
//   [4227072)  loss                      1
//   [4227073)  dist    (B,T,1024) 33,554,432  (odd float offset: NOT 16B aligned)

#define DD      128
#define NCODES  1024
#define TT      4096
#define BB      8
#define BT      (BB*TT)          // 32768
#define ZQ_ELEMS (BB*DD*TT)
#define OUT_FULL (ZQ_ELEMS + BT + 1 + (long long)BT*NCODES)
#define PREPZ_SMEM (DD * 130 * 4)    // 66560 bytes (dynamic)
// GEMM smem: Ah 32K | Al 32K | Bh 16K | Bl 16K = 96KB dynamic (A region reused as dist stage)
#define GEMM_SMEM  98304

// bf16 fragment-major prepack (mma.m16n8k16 row.col):
// A tile (128 rows): [mt(8)][ks(8)][lane(32)] x uint4
// B tile (64 codes): [nt(8)][ks(8)][lane(32)] x uint2
__device__ __align__(16) uint4 g_ah[(size_t)256 * 2048];   // 8 MB (z hi)
__device__ __align__(16) uint4 g_al[(size_t)256 * 2048];   // 8 MB (z lo)
__device__ __align__(16) uint2 g_bh[16 * 2048];            // 256 KB (cb hi)
__device__ __align__(16) uint2 g_bl[16 * 2048];            // 256 KB (cb lo)
__device__ float  g_r2[BT];
__device__ float  g_c2[NCODES];
__device__ float  g_minv[BT * 16];
__device__ int    g_mini[BT * 16];
__device__ int    g_codes[BT];
__device__ double g_partial[256];

__device__ __forceinline__ uint32_t smem_u32(const void* p) {
    uint32_t a;
    asm("{ .reg .u64 t; cvta.to.shared.u64 t, %1; cvt.u32.u64 %0, t; }" : "=r"(a) : "l"(p));
    return a;
}
__device__ __forceinline__ uint32_t packbf(float x0, float x1) {   // x0 -> low half
    unsigned short h0 = __bfloat16_as_ushort(__float2bfloat16(x0));
    unsigned short h1 = __bfloat16_as_ushort(__float2bfloat16(x1));
    return ((uint32_t)h1 << 16) | h0;
}
__device__ __forceinline__ float bfres(float x) {                   // residual after bf16 hi
    return x - __bfloat162float(__float2bfloat16(x));
}
#define MMA_BF16(accv, a0, a1, a2, a3, b0, b1) \
    asm volatile( \
        "mma.sync.aligned.m16n8k16.row.col.f32.bf16.bf16.f32 " \
        "{%0,%1,%2,%3}, {%4,%5,%6,%7}, {%8,%9}, {%0,%1,%2,%3};" \
        : "+f"((accv)[0]), "+f"((accv)[1]), "+f"((accv)[2]), "+f"((accv)[3]) \
        : "r"(a0), "r"(a1), "r"(a2), "r"(a3), "r"(b0), "r"(b1))

// --------------------------------------------------- prep z: transpose + split frags + r2
__global__ __launch_bounds__(128)
void prep_z(const float* __restrict__ z) {
    extern __shared__ float stg[];          // [DD][130]
    const int tid = threadIdx.x, bx = blockIdx.x;
    const int b = bx >> 5, t0 = (bx & 31) * 128;
    const float* zb = z + (size_t)b * DD * TT + t0;
    for (int idx = tid; idx < DD * 128; idx += 128) {
        int d = idx >> 7, tl = idx & 127;
        stg[d * 130 + tl] = zb[(size_t)d * TT + tl];
    }
    __syncthreads();
    {
        double r2 = 0.0;
        #pragma unroll 8
        for (int d = 0; d < DD; ++d) { float v = stg[d * 130 + tid]; r2 += (double)v * v; }
        g_r2[bx * 128 + tid] = (float)r2;
    }
    uint4* dh = g_ah + (size_t)bx * 2048;
    uint4* dl = g_al + (size_t)bx * 2048;
    #pragma unroll 4
    for (int i = 0; i < 16; ++i) {
        int fi = tid + i * 128;                       // 0..2047
        int lane = fi & 31, ks = (fi >> 5) & 7, mt = fi >> 8;
        int g = mt * 16 + (lane >> 2);
        int k0 = ks * 16 + (lane & 3) * 2;
        float x00 = stg[k0 * 130 + g],        x01 = stg[(k0 + 1) * 130 + g];
        float x10 = stg[k0 * 130 + g + 8],    x11 = stg[(k0 + 1) * 130 + g + 8];
        float x20 = stg[(k0 + 8) * 130 + g],  x21 = stg[(k0 + 9) * 130 + g];
        float x30 = stg[(k0 + 8) * 130 + g + 8], x31 = stg[(k0 + 9) * 130 + g + 8];
        dh[fi] = make_uint4(packbf(x00, x01), packbf(x10, x11), packbf(x20, x21), packbf(x30, x31));
        dl[fi] = make_uint4(packbf(bfres(x00), bfres(x01)), packbf(bfres(x10), bfres(x11)),
                            packbf(bfres(x20), bfres(x21)), packbf(bfres(x30), bfres(x31)));
    }
}

// --------------------------------------------------- prep codebook frags (hi + lo) + c2
__global__ __launch_bounds__(256)
void prep_c(const float* __restrict__ cb) {
    const int idx = blockIdx.x * 256 + threadIdx.x;   // < 32768
    const int r = idx & 2047, nb = idx >> 11;
    const int lane = r & 31, ks = (r >> 5) & 7, nt = r >> 8;
    const int n = nb * 64 + nt * 8 + (lane >> 2);
    const int k0 = ks * 16 + (lane & 3) * 2;
    const float* row = cb + (size_t)n * DD;
    float x00 = row[k0],     x01 = row[k0 + 1];
    float x10 = row[k0 + 8], x11 = row[k0 + 9];
    g_bh[idx] = make_uint2(packbf(x00, x01), packbf(x10, x11));
    g_bl[idx] = make_uint2(packbf(bfres(x00), bfres(x01)), packbf(bfres(x10), bfres(x11)));
    if (idx < NCODES) {
        const float* rr = cb + (size_t)idx * DD;
        double s = 0.0;
        #pragma unroll 8
        for (int d = 0; d < DD; ++d) { float v = rr[d]; s += (double)v * (double)v; }
        g_c2[idx] = (float)s;
    }
}

// --------------------------------------------------- bf16-split dist GEMM + partial argmin
// grid (256, 16): bx = 128-row tile, by = 64-code tile. 256 thr = 8 warps (2 x 4).
// warp tile 64x16. dot = zh*ch + zl*ch + zh*cl.
// k-step = 3 passes over 8 independent accumulators (RAW distance 8);
// afh/bfh/bfl register double-buffered one k-step ahead; afl loaded at k-step start.
__global__ __launch_bounds__(256, 2)
void vq_gemm(float* __restrict__ dist) {
    extern __shared__ __align__(16) unsigned char dsm[];
    __shared__ float r2s[128], c2s[64];
    __shared__ float redV[512];
    __shared__ int   redI[512];

    const int tid = threadIdx.x, lane = tid & 31, wid = tid >> 5;
    const int wm = wid & 1, wn = wid >> 1;          // rows wm*64, cols wn*16
    const int bx = blockIdx.x, by = blockIdx.y;
    const int rowbase = bx * 128, colbase = by * 64;

    const uint32_t sB = smem_u32(dsm);
    const char* gAh = (const char*)(g_ah + (size_t)bx * 2048);
    const char* gAl = (const char*)(g_al + (size_t)bx * 2048);
    const char* gBh = (const char*)(g_bh + (size_t)by * 2048);
    const char* gBl = (const char*)(g_bl + (size_t)by * 2048);
    #pragma unroll
    for (int i = 0; i < 8; ++i) {
        uint32_t o = (tid + i * 256) * 16;
        asm volatile("cp.async.cg.shared.global [%0], [%1], 16;" :: "r"(sB + o), "l"(gAh + o));
        asm volatile("cp.async.cg.shared.global [%0], [%1], 16;" :: "r"(sB + 32768 + o), "l"(gAl + o));
    }
    #pragma unroll
    for (int i = 0; i < 4; ++i) {
        uint32_t o = (tid + i * 256) * 16;
        asm volatile("cp.async.cg.shared.global [%0], [%1], 16;" :: "r"(sB + 65536 + o), "l"(gBh + o));
        asm volatile("cp.async.cg.shared.global [%0], [%1], 16;" :: "r"(sB + 81920 + o), "l"(gBl + o));
    }
    asm volatile("cp.async.commit_group;" ::: "memory");

    if (tid < 128) r2s[tid] = g_r2[rowbase + tid];
    if (tid < 64)  c2s[tid] = g_c2[colbase + tid];

    asm volatile("cp.async.wait_group 0;" ::: "memory");
    __syncthreads();

    float acc[4][2][4];
    #pragma unroll
    for (int i = 0; i < 4; ++i)
        #pragma unroll
        for (int j = 0; j < 2; ++j)
            #pragma unroll
            for (int k = 0; k < 4; ++k) acc[i][j][k] = 0.0f;

    #define A_OFF(mt, kk) ((size_t)((((wm) * 4 + (mt)) * 8 + (kk)) * 32 + lane) * 16)
    #define B_OFF(nt, kk) ((size_t)((((wn) * 2 + (nt)) * 8 + (kk)) * 32 + lane) * 8)

    uint4 afh[2][4];
    uint2 bfh[2][2], bfl[2][2];
    #pragma unroll
    for (int mt = 0; mt < 4; ++mt) afh[0][mt] = *(const uint4*)(dsm + A_OFF(mt, 0));
    #pragma unroll
    for (int nt = 0; nt < 2; ++nt) {
        bfh[0][nt] = *(const uint2*)(dsm + 65536 + B_OFF(nt, 0));
        bfl[0][nt] = *(const uint2*)(dsm + 81920 + B_OFF(nt, 0));
    }

    #pragma unroll
    for (int ks = 0; ks < 8; ++ks) {
        const int cur = ks & 1, nxt = cur ^ 1;
        // afl for this k-step: first consumed a full 8-mma pass from now
        uint4 afl[4];
        #pragma unroll
        for (int mt = 0; mt < 4; ++mt) afl[mt] = *(const uint4*)(dsm + 32768 + A_OFF(mt, ks));

        // pass 1: hi * Bh  (8 independent accumulators)
        #pragma unroll
        for (int mt = 0; mt < 4; ++mt)
            #pragma unroll
            for (int nt = 0; nt < 2; ++nt)
                MMA_BF16(acc[mt][nt], afh[cur][mt].x, afh[cur][mt].y, afh[cur][mt].z, afh[cur][mt].w,
                         bfh[cur][nt].x, bfh[cur][nt].y);

        // prefetch next k-step frags (consumed next iteration)
        if (ks < 7) {
            #pragma unroll
            for (int mt = 0; mt < 4; ++mt) afh[nxt][mt] = *(const uint4*)(dsm + A_OFF(mt, ks + 1));
            #pragma unroll
            for (int nt = 0; nt < 2; ++nt) {
                bfh[nxt][nt] = *(const uint2*)(dsm + 65536 + B_OFF(nt, ks + 1));
                bfl[nxt][nt] = *(const uint2*)(dsm + 81920 + B_OFF(nt, ks + 1));
            }
        }

        // pass 2: lo * Bh
        #pragma unroll
        for (int mt = 0; mt < 4; ++mt)
            #pragma unroll
            for (int nt = 0; nt < 2; ++nt)
                MMA_BF16(acc[mt][nt], afl[mt].x, afl[mt].y, afl[mt].z, afl[mt].w,
                         bfh[cur][nt].x, bfh[cur][nt].y);

        // pass 3: hi * Bl
        #pragma unroll
        for (int mt = 0; mt < 4; ++mt)
            #pragma unroll
            for (int nt = 0; nt < 2; ++nt)
                MMA_BF16(acc[mt][nt], afh[cur][mt].x, afh[cur][mt].y, afh[cur][mt].z, afh[cur][mt].w,
                         bfl[cur][nt].x, bfl[cur][nt].y);
    }
    #undef A_OFF
    #undef B_OFF

    __syncthreads();   // mainloop frag reads done in ALL warps before A region reuse

    // epilogue: dist = (r2 - 2*dot) + c2; stage into smem (row stride 65) + argmin
    float* stg = (float*)dsm;                 // 128 x 65 f32 = 33.3KB (fits A region + slack)
    #pragma unroll
    for (int mt = 0; mt < 4; ++mt) {
        const int r0 = wm * 64 + mt * 16 + (lane >> 2);
        const int r1 = r0 + 8;
        const float r2a = r2s[r0], r2b = r2s[r1];
        float v0 = 3.4e38f, v1 = 3.4e38f; int i0 = 0, i1 = 0;
        #pragma unroll
        for (int nt = 0; nt < 2; ++nt) {
            const int cl0 = wn * 16 + nt * 8 + (lane & 3) * 2;   // local col 0..63
            const float c20 = c2s[cl0], c21 = c2s[cl0 + 1];
            float d00 = __fadd_rn(__fsub_rn(r2a, __fmul_rn(2.0f, acc[mt][nt][0])), c20);
            float d01 = __fadd_rn(__fsub_rn(r2a, __fmul_rn(2.0f, acc[mt][nt][1])), c21);
            float d10 = __fadd_rn(__fsub_rn(r2b, __fmul_rn(2.0f, acc[mt][nt][2])), c20);
            float d11 = __fadd_rn(__fsub_rn(r2b, __fmul_rn(2.0f, acc[mt][nt][3])), c21);
            stg[r0 * 65 + cl0] = d00; stg[r0 * 65 + cl0 + 1] = d01;
            stg[r1 * 65 + cl0] = d10; stg[r1 * 65 + cl0 + 1] = d11;
            if (d00 < v0) { v0 = d00; i0 = cl0; }
            if (d01 < v0) { v0 = d01; i0 = cl0 + 1; }
            if (d10 < v1) { v1 = d10; i1 = cl0; }
            if (d11 < v1) { v1 = d11; i1 = cl0 + 1; }
        }
        #pragma unroll
        for (int off = 1; off <= 2; off <<= 1) {
            float ov = __shfl_xor_sync(0xffffffff, v0, off);
            int   oi = __shfl_xor_sync(0xffffffff, i0, off);
            if (ov < v0 || (ov == v0 && oi < i0)) { v0 = ov; i0 = oi; }
            ov = __shfl_xor_sync(0xffffffff, v1, off);
            oi = __shfl_xor_sync(0xffffffff, i1, off);
            if (ov < v1 || (ov == v1 && oi < i1)) { v1 = ov; i1 = oi; }
        }
        if ((lane & 3) == 0) {
            redV[r0 * 4 + wn] = v0; redI[r0 * 4 + wn] = i0;
            redV[r1 * 4 + wn] = v1; redI[r1 * 4 + wn] = i1;
        }
    }
    __syncthreads();

    // coalesced dist write-out: warp stores 32 consecutive floats per instr
    if (dist) {
        float* dbase = dist + (size_t)rowbase * NCODES + colbase;
        #pragma unroll
        for (int i = 0; i < 32; ++i) {
            int e = i * 256 + tid;            // 0..8191
            int r = e >> 6, c = e & 63;
            __stcs(dbase + (size_t)r * NCODES + c, stg[r * 65 + c]);
        }
    }

    if (tid < 128) {
        float bv = redV[tid * 4]; int bi = redI[tid * 4];
        #pragma unroll
        for (int w = 1; w < 4; ++w) {
            float v = redV[tid * 4 + w]; int ii = redI[tid * 4 + w];
            if (v < bv || (v == bv && ii < bi)) { bv = v; bi = ii; }
        }
        g_minv[(size_t)(rowbase + tid) * 16 + by] = bv;
        g_mini[(size_t)(rowbase + tid) * 16 + by] = colbase + bi;
    }
}

// --------------------------------------------------- cross-chunk argmin + loss partials
__global__ __launch_bounds__(128)
void combine(float* __restrict__ codesF) {
    __shared__ double s[128];
    const int tid = threadIdx.x;
    const int row = blockIdx.x * 128 + tid;
    float bv = g_minv[(size_t)row * 16]; int bi = g_mini[(size_t)row * 16];
    #pragma unroll
    for (int c = 1; c < 16; ++c) {
        float v = g_minv[(size_t)row * 16 + c]; int ii = g_mini[(size_t)row * 16 + c];
        if (v < bv || (v == bv && ii < bi)) { bv = v; bi = ii; }
    }
    g_codes[row] = bi;
    if (codesF) codesF[row] = (float)bi;
    s[tid] = (double)bv;
    __syncthreads();
    for (int o = 64; o; o >>= 1) {
        if (tid < o) s[tid] += s[tid + o];
        __syncthreads();
    }
    if (tid == 0) g_partial[blockIdx.x] = s[0];
}

// --------------------------------------------------- z_q gather (B,D,T)
__global__ void zq_kernel(const float* __restrict__ cb, float* __restrict__ zq) {
    int idx = blockIdx.x * blockDim.x + threadIdx.x;
    int t = idx & (TT - 1);
    int d = (idx >> 12) & (DD - 1);
    int b = idx >> 19;
    int code = g_codes[(b << 12) + t];
    zq[idx] = __ldg(&cb[(size_t)code * DD + d]);
}

// --------------------------------------------------- loss finalize
__global__ void fin_kernel(float* __restrict__ loss) {
    __shared__ double s[256];
    s[threadIdx.x] = g_partial[threadIdx.x];
    __syncthreads();
    for (int o = 128; o; o >>= 1) {
        if (threadIdx.x < o) s[threadIdx.x] += s[threadIdx.x + o];
        __syncthreads();
    }
    if (threadIdx.x == 0) *loss = (float)(1.25 * s[0] / (double)ZQ_ELEMS);
}

// --------------------------------------------------- launcher
extern "C" void kernel_launch(void* const* d_in, const int* in_sizes, int n_in,
                              void* d_out, int out_size) {
    const float* z  = (const float*)d_in[0];
    const float* cb = (const float*)d_in[1];
    float* out = (float*)d_out;

    float* zq     = out;
    float* codesF = nullptr;
    float* lossF  = nullptr;
    float* dist   = nullptr;
    if ((long long)out_size >= OUT_FULL) {
        codesF = out + ZQ_ELEMS;
        lossF  = codesF + BT;
        dist   = lossF + 1;
    }

    cudaFuncSetAttribute(prep_z, cudaFuncAttributeMaxDynamicSharedMemorySize, PREPZ_SMEM);
    cudaFuncSetAttribute(vq_gemm, cudaFuncAttributeMaxDynamicSharedMemorySize, GEMM_SMEM);

    prep_z<<<256, 128, PREPZ_SMEM>>>(z);
    prep_c<<<128, 256>>>(cb);
    vq_gemm<<<dim3(256, 16), 256, GEMM_SMEM>>>(dist);
    combine<<<256, 128>>>(codesF);
    zq_kernel<<<ZQ_ELEMS / 256, 256>>>(cb, zq);
    if (lossF) fin_kernel<<<1, 256>>>(lossF);
}

// round 16
// speedup vs baseline: 1.4292x; 1.0486x over previous
#include <cuda_runtime.h>
#include <cuda_bf16.h>
#include <cstdint>

// VectorQuantizer: z (8,128,4096) f32, codebook (1024,128) f32.
// Output layout (confirmed): concatenated f32
//   [0)        z_q_out (B,D,T)   4,194,304
//   [4194304)  codes   (B,T)        32,768
//   [4227072)  loss                      1
//   [4227073)  dist    (B,T,1024) 33,554,432  (odd float offset: NOT 16B aligned)

#define DD      128
#define NCODES  1024
#define TT      4096
#define BB      8
#define BT      (BB*TT)          // 32768
#define ZQ_ELEMS (BB*DD*TT)
#define OUT_FULL (ZQ_ELEMS + BT + 1 + (long long)BT*NCODES)
#define PREPZ_SMEM (DD * 130 * 4)    // 66560 bytes (dynamic)
// GEMM smem: Ah 32K | Bh 16K | Bl 16K = 64KB dynamic (Al comes via LDG; Ah region reused as dist stage)
#define GEMM_SMEM  65536

// bf16 fragment-major prepack (mma.m16n8k16 row.col):
// A tile (128 rows): [mt(8)][ks(8)][lane(32)] x uint4
// B tile (64 codes): [nt(8)][ks(8)][lane(32)] x uint2
__device__ __align__(16) uint4 g_ah[(size_t)256 * 2048];   // 8 MB (z hi)
__device__ __align__(16) uint4 g_al[(size_t)256 * 2048];   // 8 MB (z lo)
__device__ __align__(16) uint2 g_bh[16 * 2048];            // 256 KB (cb hi)
__device__ __align__(16) uint2 g_bl[16 * 2048];            // 256 KB (cb lo)
__device__ float  g_r2[BT];
__device__ float  g_c2[NCODES];
__device__ float  g_minv[BT * 16];
__device__ int    g_mini[BT * 16];
__device__ int    g_codes[BT];
__device__ double g_partial[256];

__device__ __forceinline__ uint32_t smem_u32(const void* p) {
    uint32_t a;
    asm("{ .reg .u64 t; cvta.to.shared.u64 t, %1; cvt.u32.u64 %0, t; }" : "=r"(a) : "l"(p));
    return a;
}
__device__ __forceinline__ uint32_t packbf(float x0, float x1) {   // x0 -> low half
    unsigned short h0 = __bfloat16_as_ushort(__float2bfloat16(x0));
    unsigned short h1 = __bfloat16_as_ushort(__float2bfloat16(x1));
    return ((uint32_t)h1 << 16) | h0;
}
__device__ __forceinline__ float bfres(float x) {                   // residual after bf16 hi
    return x - __bfloat162float(__float2bfloat16(x));
}
#define MMA_BF16(accv, a0, a1, a2, a3, b0, b1) \
    asm volatile( \
        "mma.sync.aligned.m16n8k16.row.col.f32.bf16.bf16.f32 " \
        "{%0,%1,%2,%3}, {%4,%5,%6,%7}, {%8,%9}, {%0,%1,%2,%3};" \
        : "+f"((accv)[0]), "+f"((accv)[1]), "+f"((accv)[2]), "+f"((accv)[3]) \
        : "r"(a0), "r"(a1), "r"(a2), "r"(a3), "r"(b0), "r"(b1))

// --------------------------------------------------- prep z: transpose + split frags + r2
__global__ __launch_bounds__(128)
void prep_z(const float* __restrict__ z) {
    extern __shared__ float stg[];          // [DD][130]
    const int tid = threadIdx.x, bx = blockIdx.x;
    const int b = bx >> 5, t0 = (bx & 31) * 128;
    const float* zb = z + (size_t)b * DD * TT + t0;
    for (int idx = tid; idx < DD * 128; idx += 128) {
        int d = idx >> 7, tl = idx & 127;
        stg[d * 130 + tl] = zb[(size_t)d * TT + tl];
    }
    __syncthreads();
    {
        double r2 = 0.0;
        #pragma unroll 8
        for (int d = 0; d < DD; ++d) { float v = stg[d * 130 + tid]; r2 += (double)v * v; }
        g_r2[bx * 128 + tid] = (float)r2;
    }
    uint4* dh = g_ah + (size_t)bx * 2048;
    uint4* dl = g_al + (size_t)bx * 2048;
    #pragma unroll 4
    for (int i = 0; i < 16; ++i) {
        int fi = tid + i * 128;                       // 0..2047
        int lane = fi & 31, ks = (fi >> 5) & 7, mt = fi >> 8;
        int g = mt * 16 + (lane >> 2);
        int k0 = ks * 16 + (lane & 3) * 2;
        float x00 = stg[k0 * 130 + g],        x01 = stg[(k0 + 1) * 130 + g];
        float x10 = stg[k0 * 130 + g + 8],    x11 = stg[(k0 + 1) * 130 + g + 8];
        float x20 = stg[(k0 + 8) * 130 + g],  x21 = stg[(k0 + 9) * 130 + g];
        float x30 = stg[(k0 + 8) * 130 + g + 8], x31 = stg[(k0 + 9) * 130 + g + 8];
        dh[fi] = make_uint4(packbf(x00, x01), packbf(x10, x11), packbf(x20, x21), packbf(x30, x31));
        dl[fi] = make_uint4(packbf(bfres(x00), bfres(x01)), packbf(bfres(x10), bfres(x11)),
                            packbf(bfres(x20), bfres(x21)), packbf(bfres(x30), bfres(x31)));
    }
}

// --------------------------------------------------- prep codebook frags (hi + lo) + c2
__global__ __launch_bounds__(256)
void prep_c(const float* __restrict__ cb) {
    const int idx = blockIdx.x * 256 + threadIdx.x;   // < 32768
    const int r = idx & 2047, nb = idx >> 11;
    const int lane = r & 31, ks = (r >> 5) & 7, nt = r >> 8;
    const int n = nb * 64 + nt * 8 + (lane >> 2);
    const int k0 = ks * 16 + (lane & 3) * 2;
    const float* row = cb + (size_t)n * DD;
    float x00 = row[k0],     x01 = row[k0 + 1];
    float x10 = row[k0 + 8], x11 = row[k0 + 9];
    g_bh[idx] = make_uint2(packbf(x00, x01), packbf(x10, x11));
    g_bl[idx] = make_uint2(packbf(bfres(x00), bfres(x01)), packbf(bfres(x10), bfres(x11)));
    if (idx < NCODES) {
        const float* rr = cb + (size_t)idx * DD;
        double s = 0.0;
        #pragma unroll 8
        for (int d = 0; d < DD; ++d) { float v = rr[d]; s += (double)v * (double)v; }
        g_c2[idx] = (float)s;
    }
}

// --------------------------------------------------- bf16-split dist GEMM + partial argmin
// grid (256, 16): bx = 128-row tile, by = 64-code tile. 256 thr = 8 warps (2 x 4).
// warp tile 64x16. dot = zh*ch + zl*ch + zh*cl.
// Occupancy push: 84 regs (3 CTAs/SM = 24 warps). Ah/Bh/Bl in smem;
// Al fragments loaded by coalesced LDG (L2-resident) with 1-k-step prefetch.
__global__ __launch_bounds__(256, 3)
void vq_gemm(float* __restrict__ dist) {
    extern __shared__ __align__(16) unsigned char dsm[];
    __shared__ float r2s[128], c2s[64];
    __shared__ float redV[512];
    __shared__ int   redI[512];

    const int tid = threadIdx.x, lane = tid & 31, wid = tid >> 5;
    const int wm = wid & 1, wn = wid >> 1;          // rows wm*64, cols wn*16
    const int bx = blockIdx.x, by = blockIdx.y;
    const int rowbase = bx * 128, colbase = by * 64;

    const uint32_t sB = smem_u32(dsm);
    const char* gAh = (const char*)(g_ah + (size_t)bx * 2048);
    const char* gBh = (const char*)(g_bh + (size_t)by * 2048);
    const char* gBl = (const char*)(g_bl + (size_t)by * 2048);
    const uint4* gAl = g_al + (size_t)bx * 2048;
    #pragma unroll
    for (int i = 0; i < 8; ++i) {
        uint32_t o = (tid + i * 256) * 16;
        asm volatile("cp.async.cg.shared.global [%0], [%1], 16;" :: "r"(sB + o), "l"(gAh + o));
    }
    #pragma unroll
    for (int i = 0; i < 4; ++i) {
        uint32_t o = (tid + i * 256) * 16;
        asm volatile("cp.async.cg.shared.global [%0], [%1], 16;" :: "r"(sB + 32768 + o), "l"(gBh + o));
        asm volatile("cp.async.cg.shared.global [%0], [%1], 16;" :: "r"(sB + 49152 + o), "l"(gBl + o));
    }
    asm volatile("cp.async.commit_group;" ::: "memory");

    if (tid < 128) r2s[tid] = g_r2[rowbase + tid];
    if (tid < 64)  c2s[tid] = g_c2[colbase + tid];

    #define A_IDX(mt, kk) ((size_t)((((wm) * 4 + (mt)) * 8 + (kk)) * 32 + lane))
    #define A_OFF(mt, kk) (A_IDX(mt, kk) * 16)
    #define B_OFF(nt, kk) ((size_t)((((wn) * 2 + (nt)) * 8 + (kk)) * 32 + lane) * 8)

    // prefetch afl for ks=0 straight from global (independent of cp.async)
    uint4 afl_c[4];
    #pragma unroll
    for (int mt = 0; mt < 4; ++mt) afl_c[mt] = __ldg(&gAl[A_IDX(mt, 0)]);

    asm volatile("cp.async.wait_group 0;" ::: "memory");
    __syncthreads();

    float acc[4][2][4];
    #pragma unroll
    for (int i = 0; i < 4; ++i)
        #pragma unroll
        for (int j = 0; j < 2; ++j)
            #pragma unroll
            for (int k = 0; k < 4; ++k) acc[i][j][k] = 0.0f;

    #pragma unroll
    for (int ks = 0; ks < 8; ++ks) {
        uint4 afh[4]; uint2 bfh[2], bfl[2];
        #pragma unroll
        for (int mt = 0; mt < 4; ++mt) afh[mt] = *(const uint4*)(dsm + A_OFF(mt, ks));
        #pragma unroll
        for (int nt = 0; nt < 2; ++nt) {
            bfh[nt] = *(const uint2*)(dsm + 32768 + B_OFF(nt, ks));
            bfl[nt] = *(const uint2*)(dsm + 49152 + B_OFF(nt, ks));
        }

        // pass 1: hi * Bh  (8 independent accumulators)
        #pragma unroll
        for (int mt = 0; mt < 4; ++mt)
            #pragma unroll
            for (int nt = 0; nt < 2; ++nt)
                MMA_BF16(acc[mt][nt], afh[mt].x, afh[mt].y, afh[mt].z, afh[mt].w,
                         bfh[nt].x, bfh[nt].y);

        // prefetch next afl (consumed next iteration's pass 2)
        uint4 afl_n[4];
        if (ks < 7) {
            #pragma unroll
            for (int mt = 0; mt < 4; ++mt) afl_n[mt] = __ldg(&gAl[A_IDX(mt, ks + 1)]);
        }

        // pass 2: lo * Bh
        #pragma unroll
        for (int mt = 0; mt < 4; ++mt)
            #pragma unroll
            for (int nt = 0; nt < 2; ++nt)
                MMA_BF16(acc[mt][nt], afl_c[mt].x, afl_c[mt].y, afl_c[mt].z, afl_c[mt].w,
                         bfh[nt].x, bfh[nt].y);

        // pass 3: hi * Bl
        #pragma unroll
        for (int mt = 0; mt < 4; ++mt)
            #pragma unroll
            for (int nt = 0; nt < 2; ++nt)
                MMA_BF16(acc[mt][nt], afh[mt].x, afh[mt].y, afh[mt].z, afh[mt].w,
                         bfl[nt].x, bfl[nt].y);

        if (ks < 7) {
            #pragma unroll
            for (int mt = 0; mt < 4; ++mt) afl_c[mt] = afl_n[mt];
        }
    }
    #undef A_IDX
    #undef A_OFF
    #undef B_OFF

    __syncthreads();   // mainloop frag reads done in ALL warps before smem reuse

    // epilogue: dist = (r2 - 2*dot) + c2; stage into smem (row stride 65) + argmin
    float* stg = (float*)dsm;                 // 128 x 65 f32 = 33.3KB (fits in 64KB dynamic)
    #pragma unroll
    for (int mt = 0; mt < 4; ++mt) {
        const int r0 = wm * 64 + mt * 16 + (lane >> 2);
        const int r1 = r0 + 8;
        const float r2a = r2s[r0], r2b = r2s[r1];
        float v0 = 3.4e38f, v1 = 3.4e38f; int i0 = 0, i1 = 0;
        #pragma unroll
        for (int nt = 0; nt < 2; ++nt) {
            const int cl0 = wn * 16 + nt * 8 + (lane & 3) * 2;   // local col 0..63
            const float c20 = c2s[cl0], c21 = c2s[cl0 + 1];
            float d00 = __fadd_rn(__fsub_rn(r2a, __fmul_rn(2.0f, acc[mt][nt][0])), c20);
            float d01 = __fadd_rn(__fsub_rn(r2a, __fmul_rn(2.0f, acc[mt][nt][1])), c21);
            float d10 = __fadd_rn(__fsub_rn(r2b, __fmul_rn(2.0f, acc[mt][nt][2])), c20);
            float d11 = __fadd_rn(__fsub_rn(r2b, __fmul_rn(2.0f, acc[mt][nt][3])), c21);
            stg[r0 * 65 + cl0] = d00; stg[r0 * 65 + cl0 + 1] = d01;
            stg[r1 * 65 + cl0] = d10; stg[r1 * 65 + cl0 + 1] = d11;
            if (d00 < v0) { v0 = d00; i0 = cl0; }
            if (d01 < v0) { v0 = d01; i0 = cl0 + 1; }
            if (d10 < v1) { v1 = d10; i1 = cl0; }
            if (d11 < v1) { v1 = d11; i1 = cl0 + 1; }
        }
        #pragma unroll
        for (int off = 1; off <= 2; off <<= 1) {
            float ov = __shfl_xor_sync(0xffffffff, v0, off);
            int   oi = __shfl_xor_sync(0xffffffff, i0, off);
            if (ov < v0 || (ov == v0 && oi < i0)) { v0 = ov; i0 = oi; }
            ov = __shfl_xor_sync(0xffffffff, v1, off);
            oi = __shfl_xor_sync(0xffffffff, i1, off);
            if (ov < v1 || (ov == v1 && oi < i1)) { v1 = ov; i1 = oi; }
        }
        if ((lane & 3) == 0) {
            redV[r0 * 4 + wn] = v0; redI[r0 * 4 + wn] = i0;
            redV[r1 * 4 + wn] = v1; redI[r1 * 4 + wn] = i1;
        }
    }
    __syncthreads();

    // coalesced dist write-out: warp stores 32 consecutive floats per instr
    if (dist) {
        float* dbase = dist + (size_t)rowbase * NCODES + colbase;
        #pragma unroll
        for (int i = 0; i < 32; ++i) {
            int e = i * 256 + tid;            // 0..8191
            int r = e >> 6, c = e & 63;
            __stcs(dbase + (size_t)r * NCODES + c, stg[r * 65 + c]);
        }
    }

    if (tid < 128) {
        float bv = redV[tid * 4]; int bi = redI[tid * 4];
        #pragma unroll
        for (int w = 1; w < 4; ++w) {
            float v = redV[tid * 4 + w]; int ii = redI[tid * 4 + w];
            if (v < bv || (v == bv && ii < bi)) { bv = v; bi = ii; }
        }
        g_minv[(size_t)(rowbase + tid) * 16 + by] = bv;
        g_mini[(size_t)(rowbase + tid) * 16 + by] = colbase + bi;
    }
}

// --------------------------------------------------- cross-chunk argmin + loss partials
__global__ __launch_bounds__(128)
void combine(float* __restrict__ codesF) {
    __shared__ double s[128];
    const int tid = threadIdx.x;
    const int row = blockIdx.x * 128 + tid;
    float bv = g_minv[(size_t)row * 16]; int bi = g_mini[(size_t)row * 16];
    #pragma unroll
    for (int c = 1; c < 16; ++c) {
        float v = g_minv[(size_t)row * 16 + c]; int ii = g_mini[(size_t)row * 16 + c];
        if (v < bv || (v == bv && ii < bi)) { bv = v; bi = ii; }
    }
    g_codes[row] = bi;
    if (codesF) codesF[row] = (float)bi;
    s[tid] = (double)bv;
    __syncthreads();
    for (int o = 64; o; o >>= 1) {
        if (tid < o) s[tid] += s[tid + o];
        __syncthreads();
    }
    if (tid == 0) g_partial[blockIdx.x] = s[0];
}

// --------------------------------------------------- z_q gather (B,D,T)
__global__ void zq_kernel(const float* __restrict__ cb, float* __restrict__ zq) {
    int idx = blockIdx.x * blockDim.x + threadIdx.x;
    int t = idx & (TT - 1);
    int d = (idx >> 12) & (DD - 1);
    int b = idx >> 19;
    int code = g_codes[(b << 12) + t];
    zq[idx] = __ldg(&cb[(size_t)code * DD + d]);
}

// --------------------------------------------------- loss finalize
__global__ void fin_kernel(float* __restrict__ loss) {
    __shared__ double s[256];
    s[threadIdx.x] = g_partial[threadIdx.x];
    __syncthreads();
    for (int o = 128; o; o >>= 1) {
        if (threadIdx.x < o) s[threadIdx.x] += s[threadIdx.x + o];
        __syncthreads();
    }
    if (threadIdx.x == 0) *loss = (float)(1.25 * s[0] / (double)ZQ_ELEMS);
}

// --------------------------------------------------- launcher
extern "C" void kernel_launch(void* const* d_in, const int* in_sizes, int n_in,
                              void* d_out, int out_size) {
    const float* z  = (const float*)d_in[0];
    const float* cb = (const float*)d_in[1];
    float* out = (float*)d_out;

    float* zq     = out;
    float* codesF = nullptr;
    float* lossF  = nullptr;
    float* dist   = nullptr;
    if ((long long)out_size >= OUT_FULL) {
        codesF = out + ZQ_ELEMS;
        lossF  = codesF + BT;
        dist   = lossF + 1;
    }

    cudaFuncSetAttribute(prep_z, cudaFuncAttributeMaxDynamicSharedMemorySize, PREPZ_SMEM);
    cudaFuncSetAttribute(vq_gemm, cudaFuncAttributeMaxDynamicSharedMemorySize, GEMM_SMEM);

    prep_z<<<256, 128, PREPZ_SMEM>>>(z);
    prep_c<<<128, 256>>>(cb);
    vq_gemm<<<dim3(256, 16), 256, GEMM_SMEM>>>(dist);
    combine<<<256, 128>>>(codesF);
    zq_kernel<<<ZQ_ELEMS / 256, 256>>>(cb, zq);
    if (lossF) fin_kernel<<<1, 256>>>(lossF);
}